// round 1
// baseline (speedup 1.0000x reference)
#include <cuda_runtime.h>
#include <cuda_bf16.h>

// FWHT over n=1024 for x[64, 1024, 512] f32, single pass.
// Decomposition: n = j*32 + i. Stages h=1..16 act on i (phase 1, registers),
// stages h=32..512 act on j (phase 2, registers after a smem transpose).
//
// Block: 256 threads = (dq in [0,8)) x (jt in [0,32)). Each thread owns one
// float4 of d (4 floats) and 32 rows along n. Grid: 64 batches * 16 d-tiles.
// Smem: 1024 rows x 8 float4 = 128 KiB (dynamic, opt-in).

#define FW_N 1024
#define FW_D 512
#define FW_DQ 8            // float4 columns per block (32 floats of d)
#define FW_THREADS 256
#define FW_SMEM_BYTES (FW_N * FW_DQ * (int)sizeof(float4))

__device__ __forceinline__ float4 f4_add(float4 a, float4 b) {
    return make_float4(a.x + b.x, a.y + b.y, a.z + b.z, a.w + b.w);
}
__device__ __forceinline__ float4 f4_sub(float4 a, float4 b) {
    return make_float4(a.x - b.x, a.y - b.y, a.z - b.z, a.w - b.w);
}

__global__ __launch_bounds__(FW_THREADS, 1)
void fwht1024_kernel(const float* __restrict__ x, float* __restrict__ y) {
    extern __shared__ float4 smem[];   // [1024][8] float4, row stride 8

    const int dq = threadIdx.x & 7;    // 0..7  : which float4 of the d-tile
    const int jt = threadIdx.x >> 3;   // 0..31 : j (phase 1) / i (phase 2)
    const int b  = blockIdx.x >> 4;    // 0..63
    const int dt = blockIdx.x & 15;    // 0..15 : d-tile

    // element offset of (b, n=0, d = dt*32 + dq*4)
    const size_t base = (size_t)b * FW_N * FW_D + (size_t)dt * 32 + (size_t)dq * 4;
    const float4* __restrict__ xin = reinterpret_cast<const float4*>(x + base);
    float4* __restrict__ yout      = reinterpret_cast<float4*>(y + base);
    const int rowstride_f4 = FW_D / 4;  // 128

    float4 v[32];

    // ---- load rows n = jt*32 + i, i = 0..31 (coalesced 128B per 8 lanes) ----
#pragma unroll
    for (int i = 0; i < 32; ++i)
        v[i] = xin[(size_t)(jt * 32 + i) * rowstride_f4];

    // ---- phase 1: FWHT_32 over i (global stages h = 1,2,4,8,16) ----
#pragma unroll
    for (int h = 1; h < 32; h <<= 1) {
#pragma unroll
        for (int i = 0; i < 32; ++i) {
            if ((i & h) == 0) {
                const int p = i | h;
                const float4 a = v[i];
                const float4 c = v[p];
                v[i] = f4_add(a, c);
                v[p] = f4_sub(a, c);
            }
        }
    }

    // ---- transpose via smem: write rows jt*32+i ----
#pragma unroll
    for (int i = 0; i < 32; ++i)
        smem[(jt * 32 + i) * FW_DQ + dq] = v[i];

    __syncthreads();

    // ---- read back rows j*32 + it, j = 0..31 (it == jt slot reuse) ----
    const int it = jt;
#pragma unroll
    for (int j = 0; j < 32; ++j)
        v[j] = smem[(j * 32 + it) * FW_DQ + dq];

    // ---- phase 2: FWHT_32 over j (global stages h = 32,...,512) ----
#pragma unroll
    for (int h = 1; h < 32; h <<= 1) {
#pragma unroll
        for (int j = 0; j < 32; ++j) {
            if ((j & h) == 0) {
                const int p = j | h;
                const float4 a = v[j];
                const float4 c = v[p];
                v[j] = f4_add(a, c);
                v[p] = f4_sub(a, c);
            }
        }
    }

    // ---- store rows n = j*32 + it (coalesced) ----
#pragma unroll
    for (int j = 0; j < 32; ++j)
        yout[(size_t)(j * 32 + it) * rowstride_f4] = v[j];
}

extern "C" void kernel_launch(void* const* d_in, const int* in_sizes, int n_in,
                              void* d_out, int out_size) {
    const float* x = (const float*)d_in[0];
    float* y = (float*)d_out;

    // Opt in to 128 KiB dynamic smem (idempotent; ignore error if repeated).
    cudaFuncSetAttribute(fwht1024_kernel,
                         cudaFuncAttributeMaxDynamicSharedMemorySize,
                         FW_SMEM_BYTES);

    const int batches = 64;
    const int dtiles  = FW_D / 32;  // 16
    dim3 grid(batches * dtiles);
    fwht1024_kernel<<<grid, FW_THREADS, FW_SMEM_BYTES>>>(x, y);
}

// round 2
// speedup vs baseline: 1.0435x; 1.0435x over previous
#include <cuda_runtime.h>
#include <cuda_bf16.h>

// FWHT over n=1024 for x[64, 1024, 512] f32, single pass.
// n = j*32 + i. Stages h=1..16 act on i (phase 1, registers); stages
// h=32..512 act on j (phase 2, registers after one smem transpose).
//
// Round 2: 128-thread CTAs, 16-float d-tile, 64 KiB smem -> 3 CTAs/SM
// (was 1), parity-swizzled smem rows for conflict-free 128-bit STS/LDS.

#define FW_N 1024
#define FW_D 512
#define FW_DQ 4              // float4 columns per CTA (16 floats of d)
#define FW_THREADS 128
#define FW_SMEM_BYTES (FW_N * FW_DQ * (int)sizeof(float4))   // 64 KiB

__device__ __forceinline__ float4 f4_add(float4 a, float4 b) {
    return make_float4(a.x + b.x, a.y + b.y, a.z + b.z, a.w + b.w);
}
__device__ __forceinline__ float4 f4_sub(float4 a, float4 b) {
    return make_float4(a.x - b.x, a.y - b.y, a.z - b.z, a.w - b.w);
}

__global__ __launch_bounds__(FW_THREADS, 3)
void fwht1024_kernel(const float* __restrict__ x, float* __restrict__ y) {
    extern __shared__ float4 smem[];   // [1024][4] float4, row = 64 B

    const int dq = threadIdx.x & 3;    // 0..3  : float4 column within d-tile
    const int jt = threadIdx.x >> 2;   // 0..31 : j (phase 1) / i (phase 2)
    const int b  = blockIdx.x >> 5;    // 0..63 : batch
    const int dt = blockIdx.x & 31;    // 0..31 : d-tile (16 floats each)

    const size_t base = (size_t)b * FW_N * FW_D + (size_t)dt * 16 + (size_t)dq * 4;
    const float4* __restrict__ xin = reinterpret_cast<const float4*>(x + base);
    float4* __restrict__ yout      = reinterpret_cast<float4*>(y + base);
    const int rs = FW_D / 4;           // row stride in float4 (128)

    float4 v[32];

    // ---- load rows n = jt*32 + i (streaming, 64B per 4-lane group) ----
#pragma unroll
    for (int i = 0; i < 32; ++i)
        v[i] = __ldcs(&xin[(size_t)(jt * 32 + i) * rs]);

    // ---- phase 1: FWHT_32 over i ----
#pragma unroll
    for (int h = 1; h < 32; h <<= 1) {
#pragma unroll
        for (int i = 0; i < 32; ++i) {
            if ((i & h) == 0) {
                const int p = i | h;
                const float4 a = v[i];
                const float4 c = v[p];
                v[i] = f4_add(a, c);
                v[p] = f4_sub(a, c);
            }
        }
    }

    // ---- transpose via smem, parity swizzle: logical (g, i) -> slot (g, i^(g&1))
    const int wsw = jt & 1;
#pragma unroll
    for (int i = 0; i < 32; ++i)
        smem[(jt * 32 + (i ^ wsw)) * FW_DQ + dq] = v[i];

    __syncthreads();

    const int it = jt;                 // thread's i index in phase 2
#pragma unroll
    for (int j = 0; j < 32; ++j)
        v[j] = smem[(j * 32 + (it ^ (j & 1))) * FW_DQ + dq];

    // ---- phase 2: FWHT_32 over j ----
#pragma unroll
    for (int h = 1; h < 32; h <<= 1) {
#pragma unroll
        for (int j = 0; j < 32; ++j) {
            if ((j & h) == 0) {
                const int p = j | h;
                const float4 a = v[j];
                const float4 c = v[p];
                v[j] = f4_add(a, c);
                v[p] = f4_sub(a, c);
            }
        }
    }

    // ---- store rows n = j*32 + it (streaming) ----
#pragma unroll
    for (int j = 0; j < 32; ++j)
        __stcs(&yout[(size_t)(j * 32 + it) * rs], v[j]);
}

extern "C" void kernel_launch(void* const* d_in, const int* in_sizes, int n_in,
                              void* d_out, int out_size) {
    const float* x = (const float*)d_in[0];
    float* y = (float*)d_out;

    cudaFuncSetAttribute(fwht1024_kernel,
                         cudaFuncAttributeMaxDynamicSharedMemorySize,
                         FW_SMEM_BYTES);

    const int batches = 64;
    const int dtiles  = FW_D / 16;    // 32
    dim3 grid(batches * dtiles);      // 2048 CTAs
    fwht1024_kernel<<<grid, FW_THREADS, FW_SMEM_BYTES>>>(x, y);
}